// round 16
// baseline (speedup 1.0000x reference)
#include <cuda_runtime.h>
#include <cstdint>

// Problem constants
#define Nn 8192
#define Dd 256
#define NBLK 64           // 8192 / 128
#define NTILES 2080       // upper triangle incl diagonal: 64*65/2
#define GRID_MAIN 152     // one CTA per SM (GB300: 152 SMs), single wave
#define ROWS_PER_CTA 54   // ceil(8192/152)

// Main SMEM layout: 2 stages x (A 32KB + B 32KB) + reduction + cls
#define STAGE_SZ 32768
#define SM_AOFF(s) ((s) * STAGE_SZ)
#define SM_BOFF(s) (65536 + (s) * STAGE_SZ)
#define SM_RED 131072      // 2048 floats: rowT 512 | rowP 512 | colT 512 | colP 512
#define SM_CLS 139264      // 8192 ints
#define SM_TOTAL 172032

// scale folds 1/T and log2(e):  sqrt(10 * log2(e))
#define SCALE_C 3.79828197f

// Scratch (__device__ globals: allocation-free rule; zero-initialized)
__device__ uint8_t g_Q[Nn * Dd];      // e4m3 rows of u * SCALE_C
__device__ int   g_cls[Nn];
__device__ float g_totP[NBLK * Nn];
__device__ float g_posP[NBLK * Nn];
__device__ int   g_barA, g_barB, g_barC;          // spin-barrier counters (reset each run)
__device__ unsigned long long g_accLL;            // fixed-point loss accumulator

// ---------------- PTX helpers (family-safe) ----------------
__device__ __forceinline__ uint32_t smem_u32(const void* p) {
    uint32_t a;
    asm("{ .reg .u64 t; cvta.to.shared.u64 t, %1; cvt.u32.u64 %0, t; }" : "=r"(a) : "l"(p));
    return a;
}
#define CP16(dst, src) asm volatile("cp.async.cg.shared.global [%0], [%1], 16;" :: "r"(dst), "l"(src))
#define CP_COMMIT() asm volatile("cp.async.commit_group;" ::: "memory")
#define CP_WAIT0() asm volatile("cp.async.wait_group 0;" ::: "memory")
#define CP_WAIT1() asm volatile("cp.async.wait_group 1;" ::: "memory")

#define LDM4(r, a) \
    asm volatile("ldmatrix.sync.aligned.m8n8.x4.shared.b16 {%0,%1,%2,%3}, [%4];" \
        : "=r"((r)[0]), "=r"((r)[1]), "=r"((r)[2]), "=r"((r)[3]) : "r"(a))

#define QMMA(c, a, b0, b1) \
    asm volatile("mma.sync.aligned.m16n8k32.row.col.f32.e4m3.e4m3.f32 " \
        "{%0,%1,%2,%3}, {%4,%5,%6,%7}, {%8,%9}, {%0,%1,%2,%3};" \
        : "+f"((c)[0]), "+f"((c)[1]), "+f"((c)[2]), "+f"((c)[3]) \
        : "r"((a)[0]), "r"((a)[1]), "r"((a)[2]), "r"((a)[3]), "r"(b0), "r"(b1))

__device__ __forceinline__ float ex2f(float x) {
    float r;
    asm("ex2.approx.f32 %0, %1;" : "=f"(r) : "f"(x));
    return r;
}
__device__ __forceinline__ unsigned long long pack2(float lo, float hi) {
    unsigned long long r;
    asm("mov.b64 %0, {%1,%2};" : "=l"(r) : "f"(lo), "f"(hi));
    return r;
}
__device__ __forceinline__ void unpack2(unsigned long long v, float& lo, float& hi) {
    asm("mov.b64 {%0,%1}, %2;" : "=f"(lo), "=f"(hi) : "l"(v));
}
#define ADD2(d, a) asm("add.rn.f32x2 %0, %0, %1;" : "+l"(d) : "l"(a))

// e4m3 pack: first PTX src -> HIGH byte, second -> LOW byte
__device__ __forceinline__ uint16_t fp8x2(float loVal, float hiVal) {
    uint16_t r;
    asm("cvt.rn.satfinite.e4m3x2.f32 %0, %1, %2;" : "=h"(r) : "f"(hiVal), "f"(loVal));
    return r;
}

// analytic triangle tile map: t -> (i, j), i<=j
__device__ __forceinline__ void tileIJ(int t, int& i, int& j) {
    int ii = 0, rem = t;
    while (rem >= NBLK - ii) { rem -= NBLK - ii; ii++; }
    i = ii; j = ii + rem;
}

// grid-wide spin barrier (all GRID_MAIN CTAs resident: single wave)
__device__ __forceinline__ void gridBarrier(int* cnt) {
    __syncthreads();
    __threadfence();
    if (threadIdx.x == 0) {
        atomicAdd(cnt, 1);
        while (*(volatile int*)cnt < GRID_MAIN) { __nanosleep(64); }
    }
    __syncthreads();
    __threadfence();
}

// ---------------- the single mega-kernel ----------------
__global__ void __launch_bounds__(512, 1) main_kernel(const float* __restrict__ emb,
                                                      const void* __restrict__ tgt,
                                                      float* __restrict__ out) {
    extern __shared__ char smem[];
    uint32_t sb = smem_u32(smem);
    int tid = threadIdx.x, lane = tid & 31, wid = tid >> 5;
    int wr = wid & 3, wc = wid >> 2;          // 4 row-warps x 4 col-warps
    int laneHi = lane >> 4;

    // ================= phase 0: detect + cls + quantize =================
    {
        // dtype detect (each CTA independently; cheap L2-resident scan)
        const int* t32 = (const int*)tgt;
        int acc = 0;
        for (int k = tid; k < Nn / 2; k += 512) acc |= t32[2 * k + 1];
        acc = __reduce_or_sync(0xffffffffu, acc);
        __shared__ int sor[16];
        __shared__ int sflag;
        if (lane == 0) sor[wid] = acc;
        __syncthreads();
        if (tid == 0) {
            int v = 0;
#pragma unroll
            for (int i = 0; i < 16; i++) v |= sor[i];
            sflag = (v == 0) ? 1 : 0;
        }
        __syncthreads();
        int is64 = sflag;
        const long long* t64 = (const long long*)tgt;
        // cls extraction: CTAs 0..15 cover all 8192 rows
        int r0 = blockIdx.x * 512 + tid;
        if (r0 < Nn) g_cls[r0] = is64 ? (int)t64[r0] : t32[r0];

        // quantize: one row per warp, strided over all 2432 warps chip-wide
        int gw = blockIdx.x * 16 + wid;
        for (int row = gw; row < Nn; row += GRID_MAIN * 16) {
            const float4* src = (const float4*)&emb[row * Dd + lane * 8];
            float4 v0 = src[0], v1 = src[1];
            float sq = v0.x * v0.x + v0.y * v0.y + v0.z * v0.z + v0.w * v0.w
                     + v1.x * v1.x + v1.y * v1.y + v1.z * v1.z + v1.w * v1.w;
#pragma unroll
            for (int o = 16; o > 0; o >>= 1) sq += __shfl_xor_sync(0xffffffffu, sq, o);
            float scale = SCALE_C / fmaxf(sqrtf(sq), 1e-8f);
            uint16_t p01 = fp8x2(v0.x * scale, v0.y * scale);
            uint16_t p23 = fp8x2(v0.z * scale, v0.w * scale);
            uint16_t p45 = fp8x2(v1.x * scale, v1.y * scale);
            uint16_t p67 = fp8x2(v1.z * scale, v1.w * scale);
            uint32_t lo = (uint32_t)p01 | ((uint32_t)p23 << 16);
            uint32_t hi = (uint32_t)p45 | ((uint32_t)p67 << 16);
            *(uint2*)&g_Q[row * Dd + lane * 8] = make_uint2(lo, hi);
        }
    }
    gridBarrier(&g_barA);     // g_Q and g_cls globally visible

    // ================= phase 1: symmetric tot+pos tiles =================
    uint32_t rowOffA[2]; int axor[2];
#pragma unroll
    for (int i = 0; i < 2; i++) {
        int r = wr * 32 + i * 16 + (lane & 15);
        rowOffA[i] = r * 256; axor[i] = r & 7;
    }
    uint32_t rowOffB[2]; int bxor[2];
#pragma unroll
    for (int g = 0; g < 2; g++) {
        int r = wc * 32 + g * 16 + (lane & 15);
        rowOffB[g] = r * 256; bxor[g] = r & 7;
    }
    int li[4];
#pragma unroll
    for (int s = 0; s < 4; s++) li[s] = wr * 32 + (s >> 1) * 16 + (s & 1) * 8 + (lane >> 2);
    int lcBase = wc * 32 + (lane & 3) * 2;

    float* redRowT = (float*)(smem + SM_RED);            // 512
    float* redRowP = redRowT + 512;                      // 512
    float* redColT = redRowP + 512;                      // 512
    float* redColP = redColT + 512;                      // 512
    int* clsSm = (int*)(smem + SM_CLS);

    for (int i = tid; i < Nn / 4; i += 512)
        ((int4*)clsSm)[i] = ((const int4*)g_cls)[i];
    // cls copy ordered vs use by the per-tile __syncthreads below

    auto loadChunk = [&](int stage, int blkA, int blkB) {
        uint32_t aBase = sb + SM_AOFF(stage);
        uint32_t bBase = sb + SM_BOFF(stage);
#pragma unroll
        for (int it = 0; it < 4; it++) {
            int idx = it * 512 + tid;
            int r = idx >> 4, c = idx & 15;
            uint32_t off = r * 256 + ((c ^ (r & 7)) << 4);
            CP16(aBase + off, (const char*)&g_Q[(blkA * 128 + r) * Dd] + c * 16);
            CP16(bBase + off, (const char*)&g_Q[(blkB * 128 + r) * Dd] + c * 16);
        }
        CP_COMMIT();
    };

    int t0 = blockIdx.x;
    int bi, bj;
    tileIJ(t0, bi, bj);
    loadChunk(0, bi, bj);

    int stage = 0;
    for (int t = t0; t < NTILES; t += GRID_MAIN) {
        bool isDiag = (bi == bj);
        int nt = t + GRID_MAIN;
        int nbi = 0, nbj = 0;
        if (nt < NTILES) {
            tileIJ(nt, nbi, nbj);
            loadChunk(stage ^ 1, nbi, nbj);
            CP_WAIT1();
        } else {
            CP_WAIT0();
        }
        __syncthreads();   // stage(t) data ready; orders prior red reads vs this tile's writes

        float cAcc[2][4][4];
#pragma unroll
        for (int i = 0; i < 2; i++)
#pragma unroll
            for (int n = 0; n < 4; n++)
#pragma unroll
                for (int v = 0; v < 4; v++) cAcc[i][n][v] = 0.f;

        uint32_t aB = sb + SM_AOFF(stage), bB = sb + SM_BOFF(stage);
#pragma unroll
        for (int ks = 0; ks < 8; ks++) {
            uint32_t a[2][4], b[2][4];
            int ch = ks * 2 + laneHi;
#pragma unroll
            for (int i = 0; i < 2; i++) LDM4(a[i], aB + rowOffA[i] + ((ch ^ axor[i]) << 4));
#pragma unroll
            for (int g = 0; g < 2; g++) LDM4(b[g], bB + rowOffB[g] + ((ch ^ bxor[g]) << 4));
#pragma unroll
            for (int i = 0; i < 2; i++)
#pragma unroll
                for (int n = 0; n < 4; n++)
                    QMMA(cAcc[i][n], a[i], b[n >> 1][n & 1], b[n >> 1][(n & 1) + 2]);
        }

        int clsR[4];
#pragma unroll
        for (int s = 0; s < 4; s++) clsR[s] = clsSm[bi * 128 + li[s]];
        int clsC0[4], clsC1[4];
#pragma unroll
        for (int n = 0; n < 4; n++) {
            int idx = bj * 128 + lcBase + n * 8;
            clsC0[n] = clsSm[idx];
            clsC1[n] = clsSm[idx + 1];
        }

        float rowPos[4] = {0.f, 0.f, 0.f, 0.f};
        float rowTot[4];
        float colPos[8];
        unsigned long long colTot2[4] = {0ull, 0ull, 0ull, 0ull};
#pragma unroll
        for (int x = 0; x < 8; x++) colPos[x] = 0.f;

        if (isDiag) {
            float rowTotS[4] = {0.f, 0.f, 0.f, 0.f};
#pragma unroll
            for (int n = 0; n < 4; n++) {
                int c0 = lcBase + n * 8, c1 = c0 + 1;
#pragma unroll
                for (int i = 0; i < 2; i++) {
                    int s0 = 2 * i, s1 = 2 * i + 1;
                    float e0 = ex2f(cAcc[i][n][0]);
                    float e1 = ex2f(cAcc[i][n][1]);
                    float e2 = ex2f(cAcc[i][n][2]);
                    float e3 = ex2f(cAcc[i][n][3]);
                    if (c0 != li[s0]) { rowTotS[s0] += e0; if (clsC0[n] == clsR[s0]) rowPos[s0] += e0; }
                    if (c1 != li[s0]) { rowTotS[s0] += e1; if (clsC1[n] == clsR[s0]) rowPos[s0] += e1; }
                    if (c0 != li[s1]) { rowTotS[s1] += e2; if (clsC0[n] == clsR[s1]) rowPos[s1] += e2; }
                    if (c1 != li[s1]) { rowTotS[s1] += e3; if (clsC1[n] == clsR[s1]) rowPos[s1] += e3; }
                }
            }
#pragma unroll
            for (int s = 0; s < 4; s++) rowTot[s] = rowTotS[s];
        } else {
            unsigned long long rowTot2[4] = {0ull, 0ull, 0ull, 0ull};
#pragma unroll
            for (int n = 0; n < 4; n++) {
#pragma unroll
                for (int i = 0; i < 2; i++) {
                    int s0 = 2 * i, s1 = 2 * i + 1;
                    float e0 = ex2f(cAcc[i][n][0]);
                    float e1 = ex2f(cAcc[i][n][1]);
                    float e2 = ex2f(cAcc[i][n][2]);
                    float e3 = ex2f(cAcc[i][n][3]);
                    unsigned long long p01 = pack2(e0, e1);
                    unsigned long long p23 = pack2(e2, e3);
                    ADD2(rowTot2[s0], p01);
                    ADD2(rowTot2[s1], p23);
                    ADD2(colTot2[n], p01);
                    ADD2(colTot2[n], p23);
                    if (clsC0[n] == clsR[s0]) { rowPos[s0] += e0; colPos[2 * n] += e0; }
                    if (clsC1[n] == clsR[s0]) { rowPos[s0] += e1; colPos[2 * n + 1] += e1; }
                    if (clsC0[n] == clsR[s1]) { rowPos[s1] += e2; colPos[2 * n] += e2; }
                    if (clsC1[n] == clsR[s1]) { rowPos[s1] += e3; colPos[2 * n + 1] += e3; }
                }
            }
#pragma unroll
            for (int s = 0; s < 4; s++) {
                float a, b;
                unpack2(rowTot2[s], a, b);
                rowTot[s] = a + b;
            }
        }

#pragma unroll
        for (int s = 0; s < 4; s++) {
            rowTot[s] += __shfl_xor_sync(0xffffffffu, rowTot[s], 1);
            rowTot[s] += __shfl_xor_sync(0xffffffffu, rowTot[s], 2);
            rowPos[s] += __shfl_xor_sync(0xffffffffu, rowPos[s], 1);
            rowPos[s] += __shfl_xor_sync(0xffffffffu, rowPos[s], 2);
        }
        if ((lane & 3) == 0) {
#pragma unroll
            for (int s = 0; s < 4; s++) {
                redRowT[wc * 128 + li[s]] = rowTot[s];
                redRowP[wc * 128 + li[s]] = rowPos[s];
            }
        }
        if (!isDiag) {
            float colT[8];
#pragma unroll
            for (int n = 0; n < 4; n++) {
                float a, b;
                unpack2(colTot2[n], a, b);
                colT[2 * n] = a; colT[2 * n + 1] = b;
            }
#pragma unroll
            for (int x = 0; x < 8; x++) {
                colT[x] += __shfl_xor_sync(0xffffffffu, colT[x], 4);
                colT[x] += __shfl_xor_sync(0xffffffffu, colT[x], 8);
                colT[x] += __shfl_xor_sync(0xffffffffu, colT[x], 16);
                colPos[x] += __shfl_xor_sync(0xffffffffu, colPos[x], 4);
                colPos[x] += __shfl_xor_sync(0xffffffffu, colPos[x], 8);
                colPos[x] += __shfl_xor_sync(0xffffffffu, colPos[x], 16);
            }
            if (lane < 4) {
#pragma unroll
                for (int n = 0; n < 4; n++) {
                    int lc = wc * 32 + n * 8 + lane * 2;
                    redColT[wr * 128 + lc]     = colT[2 * n];
                    redColT[wr * 128 + lc + 1] = colT[2 * n + 1];
                    redColP[wr * 128 + lc]     = colPos[2 * n];
                    redColP[wr * 128 + lc + 1] = colPos[2 * n + 1];
                }
            }
        }
        __syncthreads();
        if (tid < 128) {
            float rt = redRowT[tid] + redRowT[128 + tid] + redRowT[256 + tid] + redRowT[384 + tid];
            float rp = redRowP[tid] + redRowP[128 + tid] + redRowP[256 + tid] + redRowP[384 + tid];
            g_totP[bj * Nn + bi * 128 + tid] = rt;
            g_posP[bj * Nn + bi * 128 + tid] = rp;
            if (!isDiag) {
                float ct = redColT[tid] + redColT[128 + tid] + redColT[256 + tid] + redColT[384 + tid];
                float cp = redColP[tid] + redColP[128 + tid] + redColP[256 + tid] + redColP[384 + tid];
                g_totP[bi * Nn + bj * 128 + tid] = ct;
                g_posP[bi * Nn + bj * 128 + tid] = cp;
            }
        }
        // no trailing __syncthreads: next iteration's post-CP_WAIT sync orders reuse

        bi = nbi; bj = nbj; stage ^= 1;
    }

    gridBarrier(&g_barB);     // all partials visible

    // ================= phase 2: finalize (54 rows/CTA, 4 threads/row) =================
    {
        int lrow = tid >> 2;
        int part = tid & 3;
        int row = blockIdx.x * ROWS_PER_CTA + lrow;
        long long myll = 0;
        if (lrow < ROWS_PER_CTA && row < Nn) {
            float tt = 0.f, pp = 0.f;
#pragma unroll
            for (int s = 0; s < 16; s++) {
                int slot = part * 16 + s;
                tt += g_totP[slot * Nn + row];
                pp += g_posP[slot * Nn + row];
            }
            tt += __shfl_xor_sync(0xffffffffu, tt, 1);
            tt += __shfl_xor_sync(0xffffffffu, tt, 2);
            pp += __shfl_xor_sync(0xffffffffu, pp, 1);
            pp += __shfl_xor_sync(0xffffffffu, pp, 2);
            if (part == 0) {
                float local = logf(tt - pp) - logf(pp);
                myll = __double2ll_rn((double)local * 4294967296.0);
            }
        } else {
            // keep shfl participation uniform below
            __shfl_xor_sync(0xffffffffu, 0.f, 1);
            __shfl_xor_sync(0xffffffffu, 0.f, 2);
            __shfl_xor_sync(0xffffffffu, 0.f, 1);
            __shfl_xor_sync(0xffffffffu, 0.f, 2);
        }
#pragma unroll
        for (int o = 16; o > 0; o >>= 1)
            myll += __shfl_down_sync(0xffffffffu, myll, o);
        long long* smLL = (long long*)(smem + SM_RED);
        if (lane == 0) smLL[wid] = myll;
        __syncthreads();
        if (tid == 0) {
            long long tot = 0;
#pragma unroll
            for (int i = 0; i < 16; i++) tot += smLL[i];
            atomicAdd(&g_accLL, (unsigned long long)tot);
            __threadfence();
            int tk = atomicAdd(&g_barC, 1);
            if (tk == GRID_MAIN - 1) {
                unsigned long long v = atomicAdd(&g_accLL, 0ull);
                out[0] = (float)((double)(long long)v / 4294967296.0);
                // reset for next CUDA-graph replay (deterministic: all CTAs past all uses)
                g_accLL = 0ull;
                g_barA = 0; g_barB = 0; g_barC = 0;
            }
        }
    }
}

extern "C" void kernel_launch(void* const* d_in, const int* in_sizes, int n_in,
                              void* d_out, int out_size) {
    const float* emb = (const float*)d_in[0];
    const void* tgt = d_in[1];

    cudaFuncSetAttribute(main_kernel, cudaFuncAttributeMaxDynamicSharedMemorySize, SM_TOTAL);
    main_kernel<<<GRID_MAIN, 512, SM_TOTAL>>>(emb, tgt, (float*)d_out);
}

// round 17
// speedup vs baseline: 1.1988x; 1.1988x over previous
#include <cuda_runtime.h>
#include <cstdint>

// Problem constants
#define Nn 8192
#define Dd 256
#define NBLK 64           // 8192 / 128
#define NTILES 2080       // upper triangle incl diagonal: 64*65/2
#define GRID_MAIN 152

// Main SMEM layout: 2 stages x (A 32KB + B 32KB) + 2x reduction + cls
#define STAGE_SZ 32768
#define SM_AOFF(s) ((s) * STAGE_SZ)
#define SM_BOFF(s) (65536 + (s) * STAGE_SZ)
#define SM_RED 131072      // 2 buffers x 2048 floats (rowT 512 | rowP 512 | colT 512 | colP 512)
#define SM_CLS 147456      // 8192 ints
#define SM_TOTAL 180224

// scale folds 1/T and log2(e):  sqrt(10 * log2(e))
#define SCALE_C 3.79828197f

// Scratch (__device__ globals: allocation-free rule)
__device__ uint8_t g_Q[Nn * Dd];      // e4m3 rows of u * SCALE_C
__device__ int   g_cls[Nn];
__device__ float g_totP[NBLK * Nn];
__device__ float g_posP[NBLK * Nn];
__device__ float g_lossP[256];
__device__ unsigned char g_ti[NTILES], g_tj[NTILES];

// ---------------- PTX helpers (family-safe) ----------------
__device__ __forceinline__ uint32_t smem_u32(const void* p) {
    uint32_t a;
    asm("{ .reg .u64 t; cvta.to.shared.u64 t, %1; cvt.u32.u64 %0, t; }" : "=r"(a) : "l"(p));
    return a;
}
#define CP16(dst, src) asm volatile("cp.async.cg.shared.global [%0], [%1], 16;" :: "r"(dst), "l"(src))
#define CP_COMMIT() asm volatile("cp.async.commit_group;" ::: "memory")
#define CP_WAIT0() asm volatile("cp.async.wait_group 0;" ::: "memory")
#define CP_WAIT1() asm volatile("cp.async.wait_group 1;" ::: "memory")

#define LDM4(r, a) \
    asm volatile("ldmatrix.sync.aligned.m8n8.x4.shared.b16 {%0,%1,%2,%3}, [%4];" \
        : "=r"((r)[0]), "=r"((r)[1]), "=r"((r)[2]), "=r"((r)[3]) : "r"(a))

#define QMMA(c, a, b0, b1) \
    asm volatile("mma.sync.aligned.m16n8k32.row.col.f32.e4m3.e4m3.f32 " \
        "{%0,%1,%2,%3}, {%4,%5,%6,%7}, {%8,%9}, {%0,%1,%2,%3};" \
        : "+f"((c)[0]), "+f"((c)[1]), "+f"((c)[2]), "+f"((c)[3]) \
        : "r"((a)[0]), "r"((a)[1]), "r"((a)[2]), "r"((a)[3]), "r"(b0), "r"(b1))

__device__ __forceinline__ float ex2f(float x) {
    float r;
    asm("ex2.approx.f32 %0, %1;" : "=f"(r) : "f"(x));
    return r;
}
__device__ __forceinline__ unsigned long long pack2(float lo, float hi) {
    unsigned long long r;
    asm("mov.b64 %0, {%1,%2};" : "=l"(r) : "f"(lo), "f"(hi));
    return r;
}
__device__ __forceinline__ void unpack2(unsigned long long v, float& lo, float& hi) {
    asm("mov.b64 {%0,%1}, %2;" : "=f"(lo), "=f"(hi) : "l"(v));
}
#define ADD2(d, a) asm("add.rn.f32x2 %0, %0, %1;" : "+l"(d) : "l"(a))

// e4m3 pack: first PTX src -> HIGH byte, second -> LOW byte
__device__ __forceinline__ uint16_t fp8x2(float loVal, float hiVal) {
    uint16_t r;
    asm("cvt.rn.satfinite.e4m3x2.f32 %0, %1, %2;" : "=h"(r) : "f"(hiVal), "f"(loVal));
    return r;
}

// ---------------- merged setup: norm/quantize (blocks 0..1023) + detcls (block 1024) ----------------
__global__ void setup_kernel(const float* __restrict__ emb, const void* __restrict__ tgt) {
    int tid = threadIdx.x;
    if (blockIdx.x == Nn / 8) {
        // ---- detcls work ----
        __shared__ int sflag;
        const int* t32 = (const int*)tgt;
        int acc = 0;
        for (int k = tid; k < Nn / 2; k += 256) acc |= t32[2 * k + 1];
        acc = __reduce_or_sync(0xffffffffu, acc);
        __shared__ int sor[8];
        if ((tid & 31) == 0) sor[tid >> 5] = acc;
        __syncthreads();
        if (tid == 0) {
            int v = 0;
#pragma unroll
            for (int i = 0; i < 8; i++) v |= sor[i];
            sflag = (v == 0) ? 1 : 0;
        }
        __syncthreads();
        int is64 = sflag;
        const long long* t64 = (const long long*)tgt;
        for (int r = tid; r < Nn; r += 256)
            g_cls[r] = is64 ? (int)t64[r] : t32[r];
        for (int tt = tid; tt < NTILES; tt += 256) {
            int i = 0, rem = tt;
            while (rem >= NBLK - i) { rem -= NBLK - i; i++; }
            g_ti[tt] = (unsigned char)i;
            g_tj[tt] = (unsigned char)(i + rem);
        }
        return;
    }
    // ---- normalize + e4m3 quantize: warp per row ----
    int lane = tid & 31, wid = tid >> 5;
    int row = blockIdx.x * 8 + wid;
    const float4* src = (const float4*)&emb[row * Dd + lane * 8];
    float4 v0 = src[0], v1 = src[1];
    float v[8] = {v0.x, v0.y, v0.z, v0.w, v1.x, v1.y, v1.z, v1.w};
    float sq = 0.f;
#pragma unroll
    for (int i = 0; i < 8; i++) sq += v[i] * v[i];
#pragma unroll
    for (int o = 16; o > 0; o >>= 1) sq += __shfl_xor_sync(0xffffffffu, sq, o);
    float scale = SCALE_C / fmaxf(sqrtf(sq), 1e-8f);
    uint16_t p01 = fp8x2(v[0] * scale, v[1] * scale);
    uint16_t p23 = fp8x2(v[2] * scale, v[3] * scale);
    uint16_t p45 = fp8x2(v[4] * scale, v[5] * scale);
    uint16_t p67 = fp8x2(v[6] * scale, v[7] * scale);
    uint32_t lo = (uint32_t)p01 | ((uint32_t)p23 << 16);
    uint32_t hi = (uint32_t)p45 | ((uint32_t)p67 << 16);
    *(uint2*)&g_Q[row * Dd + lane * 8] = make_uint2(lo, hi);
}

// ---------------- main fused symmetric FP8-MMA kernel (tot + pos) ----------------
__device__ __forceinline__ void loadChunk(uint32_t sb, int stage, int blkA, int blkB, int tid) {
    uint32_t aBase = sb + SM_AOFF(stage);
    uint32_t bBase = sb + SM_BOFF(stage);
#pragma unroll
    for (int it = 0; it < 4; it++) {
        int idx = it * 512 + tid;
        int r = idx >> 4, c = idx & 15;
        uint32_t off = r * 256 + ((c ^ (r & 7)) << 4);
        CP16(aBase + off, (const char*)&g_Q[(blkA * 128 + r) * Dd] + c * 16);
        CP16(bBase + off, (const char*)&g_Q[(blkB * 128 + r) * Dd] + c * 16);
    }
    CP_COMMIT();
}

__global__ void __launch_bounds__(512, 1) main_kernel() {
    extern __shared__ char smem[];
    uint32_t sb = smem_u32(smem);
    int tid = threadIdx.x, lane = tid & 31, wid = tid >> 5;
    int wr = wid & 3, wc = wid >> 2;          // 4 row-warps x 4 col-warps
    int laneHi = lane >> 4;

    uint32_t rowOffA[2]; int axor[2];
#pragma unroll
    for (int i = 0; i < 2; i++) {
        int r = wr * 32 + i * 16 + (lane & 15);
        rowOffA[i] = r * 256; axor[i] = r & 7;
    }
    uint32_t rowOffB[2]; int bxor[2];
#pragma unroll
    for (int g = 0; g < 2; g++) {
        int r = wc * 32 + g * 16 + (lane & 15);
        rowOffB[g] = r * 256; bxor[g] = r & 7;
    }
    int li[4];
#pragma unroll
    for (int s = 0; s < 4; s++) li[s] = wr * 32 + (s >> 1) * 16 + (s & 1) * 8 + (lane >> 2);
    int lcBase = wc * 32 + (lane & 3) * 2;

    int* clsSm = (int*)(smem + SM_CLS);
    for (int i = tid; i < Nn / 4; i += 512)
        ((int4*)clsSm)[i] = ((const int4*)g_cls)[i];

    int t0 = blockIdx.x;
    if (t0 >= NTILES) return;
    int bi = g_ti[t0], bj = g_tj[t0];
    loadChunk(sb, 0, bi, bj, tid);

    int stage = 0;
    int buf = 0;
    int pbi = -1, pbj = -1, pdiag = 0, pbuf = 0;

    for (int t = t0; t < NTILES; t += GRID_MAIN) {
        bool isDiag = (bi == bj);
        int nt = t + GRID_MAIN;
        int nbi = 0, nbj = 0;
        if (nt < NTILES) {
            nbi = g_ti[nt]; nbj = g_tj[nt];
            loadChunk(sb, stage ^ 1, nbi, nbj, tid);
            CP_WAIT1();
        } else {
            CP_WAIT0();
        }
        __syncthreads();   // stage(t) ready; red(prev) writes all visible

        // per-tile red buffers (double-buffered)
        float* redRowT = (float*)(smem + SM_RED) + buf * 2048;   // 512
        float* redRowP = redRowT + 512;
        float* redColT = redRowP + 512;
        float* redColP = redColT + 512;

        // ---- deferred flush of previous tile (reads buffer !buf) ----
        if (pbi >= 0 && tid < 128) {
            float* pRowT = (float*)(smem + SM_RED) + pbuf * 2048;
            float* pRowP = pRowT + 512;
            float* pColT = pRowP + 512;
            float* pColP = pColT + 512;
            float rt = pRowT[tid] + pRowT[128 + tid] + pRowT[256 + tid] + pRowT[384 + tid];
            float rp = pRowP[tid] + pRowP[128 + tid] + pRowP[256 + tid] + pRowP[384 + tid];
            g_totP[pbj * Nn + pbi * 128 + tid] = rt;
            g_posP[pbj * Nn + pbi * 128 + tid] = rp;
            if (!pdiag) {
                float ct = pColT[tid] + pColT[128 + tid] + pColT[256 + tid] + pColT[384 + tid];
                float cp = pColP[tid] + pColP[128 + tid] + pColP[256 + tid] + pColP[384 + tid];
                g_totP[pbi * Nn + pbj * 128 + tid] = ct;
                g_posP[pbi * Nn + pbj * 128 + tid] = cp;
            }
        }

        float cAcc[2][4][4];
#pragma unroll
        for (int i = 0; i < 2; i++)
#pragma unroll
            for (int n = 0; n < 4; n++)
#pragma unroll
                for (int v = 0; v < 4; v++) cAcc[i][n][v] = 0.f;

        uint32_t aB = sb + SM_AOFF(stage), bB = sb + SM_BOFF(stage);
#pragma unroll
        for (int ks = 0; ks < 8; ks++) {
            uint32_t a[2][4], b[2][4];
            int ch = ks * 2 + laneHi;
#pragma unroll
            for (int i = 0; i < 2; i++) LDM4(a[i], aB + rowOffA[i] + ((ch ^ axor[i]) << 4));
#pragma unroll
            for (int g = 0; g < 2; g++) LDM4(b[g], bB + rowOffB[g] + ((ch ^ bxor[g]) << 4));
#pragma unroll
            for (int i = 0; i < 2; i++)
#pragma unroll
                for (int n = 0; n < 4; n++)
                    QMMA(cAcc[i][n], a[i], b[n >> 1][n & 1], b[n >> 1][(n & 1) + 2]);
        }

        // ---- per-tile class tables ----
        int clsR[4];
#pragma unroll
        for (int s = 0; s < 4; s++) clsR[s] = clsSm[bi * 128 + li[s]];
        int clsC0[4], clsC1[4];
#pragma unroll
        for (int n = 0; n < 4; n++) {
            int idx = bj * 128 + lcBase + n * 8;
            clsC0[n] = clsSm[idx];
            clsC1[n] = clsSm[idx + 1];
        }

        // ---- fused epilogue: ex2 + tot (packed) + pos (predicated) ----
        float rowPos[4] = {0.f, 0.f, 0.f, 0.f};
        float rowTot[4];
        float colPos[8];
        unsigned long long colTot2[4] = {0ull, 0ull, 0ull, 0ull};
#pragma unroll
        for (int x = 0; x < 8; x++) colPos[x] = 0.f;

        if (isDiag) {
            float rowTotS[4] = {0.f, 0.f, 0.f, 0.f};
#pragma unroll
            for (int n = 0; n < 4; n++) {
                int c0 = lcBase + n * 8, c1 = c0 + 1;
#pragma unroll
                for (int i = 0; i < 2; i++) {
                    int s0 = 2 * i, s1 = 2 * i + 1;
                    float e0 = ex2f(cAcc[i][n][0]);
                    float e1 = ex2f(cAcc[i][n][1]);
                    float e2 = ex2f(cAcc[i][n][2]);
                    float e3 = ex2f(cAcc[i][n][3]);
                    if (c0 != li[s0]) { rowTotS[s0] += e0; if (clsC0[n] == clsR[s0]) rowPos[s0] += e0; }
                    if (c1 != li[s0]) { rowTotS[s0] += e1; if (clsC1[n] == clsR[s0]) rowPos[s0] += e1; }
                    if (c0 != li[s1]) { rowTotS[s1] += e2; if (clsC0[n] == clsR[s1]) rowPos[s1] += e2; }
                    if (c1 != li[s1]) { rowTotS[s1] += e3; if (clsC1[n] == clsR[s1]) rowPos[s1] += e3; }
                }
            }
#pragma unroll
            for (int s = 0; s < 4; s++) rowTot[s] = rowTotS[s];
        } else {
            unsigned long long rowTot2[4] = {0ull, 0ull, 0ull, 0ull};
#pragma unroll
            for (int n = 0; n < 4; n++) {
#pragma unroll
                for (int i = 0; i < 2; i++) {
                    int s0 = 2 * i, s1 = 2 * i + 1;
                    float e0 = ex2f(cAcc[i][n][0]);
                    float e1 = ex2f(cAcc[i][n][1]);
                    float e2 = ex2f(cAcc[i][n][2]);
                    float e3 = ex2f(cAcc[i][n][3]);
                    unsigned long long p01 = pack2(e0, e1);
                    unsigned long long p23 = pack2(e2, e3);
                    ADD2(rowTot2[s0], p01);
                    ADD2(rowTot2[s1], p23);
                    ADD2(colTot2[n], p01);
                    ADD2(colTot2[n], p23);
                    if (clsC0[n] == clsR[s0]) { rowPos[s0] += e0; colPos[2 * n] += e0; }
                    if (clsC1[n] == clsR[s0]) { rowPos[s0] += e1; colPos[2 * n + 1] += e1; }
                    if (clsC0[n] == clsR[s1]) { rowPos[s1] += e2; colPos[2 * n] += e2; }
                    if (clsC1[n] == clsR[s1]) { rowPos[s1] += e3; colPos[2 * n + 1] += e3; }
                }
            }
#pragma unroll
            for (int s = 0; s < 4; s++) {
                float a, b;
                unpack2(rowTot2[s], a, b);
                rowTot[s] = a + b;
            }
        }

        // row reduce: lanes sharing a row differ in lane&3
#pragma unroll
        for (int s = 0; s < 4; s++) {
            rowTot[s] += __shfl_xor_sync(0xffffffffu, rowTot[s], 1);
            rowTot[s] += __shfl_xor_sync(0xffffffffu, rowTot[s], 2);
            rowPos[s] += __shfl_xor_sync(0xffffffffu, rowPos[s], 1);
            rowPos[s] += __shfl_xor_sync(0xffffffffu, rowPos[s], 2);
        }
        if ((lane & 3) == 0) {
#pragma unroll
            for (int s = 0; s < 4; s++) {
                redRowT[wc * 128 + li[s]] = rowTot[s];
                redRowP[wc * 128 + li[s]] = rowPos[s];
            }
        }
        if (!isDiag) {
            float colT[8];
#pragma unroll
            for (int n = 0; n < 4; n++) {
                float a, b;
                unpack2(colTot2[n], a, b);
                colT[2 * n] = a; colT[2 * n + 1] = b;
            }
#pragma unroll
            for (int x = 0; x < 8; x++) {
                colT[x] += __shfl_xor_sync(0xffffffffu, colT[x], 4);
                colT[x] += __shfl_xor_sync(0xffffffffu, colT[x], 8);
                colT[x] += __shfl_xor_sync(0xffffffffu, colT[x], 16);
                colPos[x] += __shfl_xor_sync(0xffffffffu, colPos[x], 4);
                colPos[x] += __shfl_xor_sync(0xffffffffu, colPos[x], 8);
                colPos[x] += __shfl_xor_sync(0xffffffffu, colPos[x], 16);
            }
            if (lane < 4) {
#pragma unroll
                for (int n = 0; n < 4; n++) {
                    int lc = wc * 32 + n * 8 + lane * 2;
                    redColT[wr * 128 + lc]     = colT[2 * n];
                    redColT[wr * 128 + lc + 1] = colT[2 * n + 1];
                    redColP[wr * 128 + lc]     = colPos[2 * n];
                    redColP[wr * 128 + lc + 1] = colPos[2 * n + 1];
                }
            }
        }
        // NO second sync: next iteration's top __syncthreads orders red(t) writes
        // before flush(t) reads; double-buffered red prevents write/read overlap.

        pbi = bi; pbj = bj; pdiag = isDiag ? 1 : 0; pbuf = buf;
        bi = nbi; bj = nbj; stage ^= 1; buf ^= 1;
    }

    // final flush
    __syncthreads();
    if (pbi >= 0 && tid < 128) {
        float* pRowT = (float*)(smem + SM_RED) + pbuf * 2048;
        float* pRowP = pRowT + 512;
        float* pColT = pRowP + 512;
        float* pColP = pColT + 512;
        float rt = pRowT[tid] + pRowT[128 + tid] + pRowT[256 + tid] + pRowT[384 + tid];
        float rp = pRowP[tid] + pRowP[128 + tid] + pRowP[256 + tid] + pRowP[384 + tid];
        g_totP[pbj * Nn + pbi * 128 + tid] = rt;
        g_posP[pbj * Nn + pbi * 128 + tid] = rp;
        if (!pdiag) {
            float ct = pColT[tid] + pColT[128 + tid] + pColT[256 + tid] + pColT[384 + tid];
            float cp = pColP[tid] + pColP[128 + tid] + pColP[256 + tid] + pColP[384 + tid];
            g_totP[pbi * Nn + pbj * 128 + tid] = ct;
            g_posP[pbi * Nn + pbj * 128 + tid] = cp;
        }
    }
}

// ---------------- finalize: 4 threads per row for MLP + parallelism ----------------
__global__ void finalize1_kernel() {
    int tid = threadIdx.x;
    int r = blockIdx.x * 32 + (tid >> 2);
    int part = tid & 3;
    float tt = 0.f, pp = 0.f;
#pragma unroll
    for (int s = 0; s < 16; s++) {
        int slot = part * 16 + s;
        tt += g_totP[slot * Nn + r];
        pp += g_posP[slot * Nn + r];
    }
    tt += __shfl_xor_sync(0xffffffffu, tt, 1);
    tt += __shfl_xor_sync(0xffffffffu, tt, 2);
    pp += __shfl_xor_sync(0xffffffffu, pp, 1);
    pp += __shfl_xor_sync(0xffffffffu, pp, 2);
    float local = (part == 0) ? (logf(tt - pp) - logf(pp)) : 0.f;
#pragma unroll
    for (int o = 16; o > 0; o >>= 1) local += __shfl_down_sync(0xffffffffu, local, o);
    __shared__ float sm[4];
    if ((tid & 31) == 0) sm[tid >> 5] = local;
    __syncthreads();
    if (tid == 0) g_lossP[blockIdx.x] = sm[0] + sm[1] + sm[2] + sm[3];
}

__global__ void finalize2_kernel(float* __restrict__ out) {
    int t = threadIdx.x;
    float v = g_lossP[t];
#pragma unroll
    for (int o = 16; o > 0; o >>= 1) v += __shfl_down_sync(0xffffffffu, v, o);
    __shared__ float sm[8];
    if ((t & 31) == 0) sm[t >> 5] = v;
    __syncthreads();
    if (t == 0) {
        float tot = 0.f;
#pragma unroll
        for (int i = 0; i < 8; i++) tot += sm[i];
        out[0] = tot;
    }
}

extern "C" void kernel_launch(void* const* d_in, const int* in_sizes, int n_in,
                              void* d_out, int out_size) {
    const float* emb = (const float*)d_in[0];
    const void* tgt = d_in[1];

    cudaFuncSetAttribute(main_kernel, cudaFuncAttributeMaxDynamicSharedMemorySize, SM_TOTAL);

    setup_kernel<<<Nn / 8 + 1, 256>>>(emb, tgt);
    main_kernel<<<GRID_MAIN, 512, SM_TOTAL>>>();
    finalize1_kernel<<<256, 128>>>();
    finalize2_kernel<<<1, 256>>>((float*)d_out);
}